// round 11
// baseline (speedup 1.0000x reference)
#include <cuda_runtime.h>

#define BB 8192
#define DD 64
#define KK 32
#define HID 16

#define NC   2048                 // cells per (k,d) column
#define XLO  (-6.0f)
#define INVD 170.6666667f         // NC / 12
#define IOFF 1024.0f              // -XLO * INVD  (exact)
#define DCH  4                    // d's per main block

// -------- device scratch (written by prep kernels, no allocations) --------
__device__ float2 g_tab[KK * DD * NC];        // 33.5 MB segment table (S,B)
__device__ float  g_xT[DD * BB];              // 2 MB   x transposed [d][b]
__device__ float  g_part[KK * (DD / DCH) * BB]; // 16 MB partial sums
__device__ float  g_oPack[KK * 32];           // outer nets: [0:16)=A, [16:32)=t
__device__ float  g_oL[KK];
__device__ float  g_oC[KK];

// ---------------------------------------------------------------------------
// Prep: block per (k,d). Thread 0: transform + sort knots + prefix sums.
// All threads: fill the 2048-cell table.
// f(x) = sum_h A_h*max(x,t_h) + L*x + C ; sorted knots give 17 segments:
//   S_j = L + sum_{i<j} A_(i) ;  B_j = C + sum_{i>=j} A_(i)*t_(i)
// A*t computed exactly as -/+ c*b (avoids inf when w1 ~ 0).
// ---------------------------------------------------------------------------
__global__ void kan_prep(const float* __restrict__ iw1, const float* __restrict__ ib1,
                         const float* __restrict__ iw2, const float* __restrict__ ib2,
                         const float* __restrict__ ow1, const float* __restrict__ ob1,
                         const float* __restrict__ ow2, const float* __restrict__ ob2) {
    __shared__ float sTs[16], sS[17], sB[17];
    const int kd = blockIdx.x;        // 0 .. KK*DD-1
    const int t  = threadIdx.x;       // 128 threads

    if (t == 0) {
        float A[16], T[16], P[16];
        float L = 0.f, C = ib2[kd];
#pragma unroll
        for (int h = 0; h < HID; h++) {
            float a = iw1[kd * HID + h];
            float b = ib1[kd * HID + h];
            float c = iw2[kd * HID + h];
            float ac = a * c;
            if (a > 0.f)      { A[h] =  ac; T[h] = -b / a; P[h] = -c * b; C += c * b; }
            else if (a < 0.f) { A[h] = -ac; T[h] = -b / a; P[h] =  c * b; L += ac; }
            else              { A[h] = 0.f; T[h] = 0.f;    P[h] = 0.f;    C += c * fmaxf(b, 0.f); }
        }
        // insertion sort by T (A,P permuted along)
        for (int i = 1; i < 16; i++) {
            float tk = T[i], ak = A[i], pk = P[i];
            int j = i - 1;
            while (j >= 0 && T[j] > tk) {
                T[j + 1] = T[j]; A[j + 1] = A[j]; P[j + 1] = P[j]; j--;
            }
            T[j + 1] = tk; A[j + 1] = ak; P[j + 1] = pk;
        }
        sS[0] = L;
        for (int j = 1; j <= 16; j++) sS[j] = sS[j - 1] + A[j - 1];
        sB[16] = C;
        for (int j = 15; j >= 0; j--) sB[j] = sB[j + 1] + P[j];
        for (int i = 0; i < 16; i++) sTs[i] = T[i];
    }

    // Outer-net transform piggyback: blocks 0..31, thread 1.
    if (t == 1 && kd < KK) {
        int k = kd;
        float Lo = 0.f, Co = ob2[k];
#pragma unroll
        for (int h = 0; h < HID; h++) {
            float a = ow1[k * HID + h], b = ob1[k * HID + h], c = ow2[k * HID + h];
            float ac = a * c, A2, tt;
            if (a > 0.f)      { A2 = ac;  tt = -b / a; Co += c * b; }
            else if (a < 0.f) { A2 = -ac; tt = -b / a; Lo += ac; }
            else              { A2 = 0.f; tt = 0.f;    Co += c * fmaxf(b, 0.f); }
            g_oPack[k * 32 + h]      = A2;
            g_oPack[k * 32 + 16 + h] = tt;
        }
        g_oL[k] = Lo;
        g_oC[k] = Co;
    }
    __syncthreads();

    // Fill cells: segment of the cell midpoint (exact when no knot inside).
    for (int c = t; c < NC; c += blockDim.x) {
        float m = XLO + (c + 0.5f) * (1.0f / INVD);
        int j = 0;
#pragma unroll
        for (int i = 0; i < 16; i++) j += (sTs[i] <= m) ? 1 : 0;
        g_tab[kd * NC + c] = make_float2(sS[j], sB[j]);
    }
}

// ---------------------------------------------------------------------------
// x transpose: x[b][d] -> g_xT[d][b], 64x64 tiles.
// ---------------------------------------------------------------------------
__global__ void kan_xT(const float* __restrict__ x) {
    __shared__ float tile[64][65];
    const int t  = threadIdx.x;       // 256
    const int b0 = blockIdx.x * 64;   // 128 blocks

#pragma unroll
    for (int i = 0; i < 4; i++) {
        int idx = t + i * 256;        // 0..1023
        int row = idx >> 4;           // b local
        int c4  = idx & 15;
        float4 v = ((const float4*)(x + (long)(b0 + row) * DD))[c4];
        tile[row][c4 * 4 + 0] = v.x;
        tile[row][c4 * 4 + 1] = v.y;
        tile[row][c4 * 4 + 2] = v.z;
        tile[row][c4 * 4 + 3] = v.w;
    }
    __syncthreads();
#pragma unroll
    for (int i = 0; i < 4; i++) {
        int idx = t + i * 256;
        int d  = idx >> 4;
        int c4 = idx & 15;
        float4 v = make_float4(tile[c4 * 4 + 0][d], tile[c4 * 4 + 1][d],
                               tile[c4 * 4 + 2][d], tile[c4 * 4 + 3][d]);
        ((float4*)(g_xT + (long)d * BB + b0))[c4] = v;
    }
}

// ---------------------------------------------------------------------------
// Main: block = (k, d-chunk of 4). Table columns in smem; loop over all b.
// Per eval: idx-FMA, F2I, clamp x2, LDS.64, FMA, FADD  (~9 inst vs 33).
// ---------------------------------------------------------------------------
__global__ void __launch_bounds__(256, 3)
kan_main() {
    extern __shared__ float2 scol[];          // DCH*NC float2 = 64 KB
    const int t  = threadIdx.x;
    const int bx = blockIdx.x;                // 0..511
    const int k  = bx >> 4;
    const int d0 = (bx & 15) * DCH;

    // stage 4 table columns (coalesced)
    {
        const float4* src = (const float4*)(g_tab + (k * DD + d0) * NC);
        float4* dst = (float4*)scol;
#pragma unroll
        for (int i = 0; i < (DCH * NC * 2 / 4) / 256; i++)   // 16 iters
            dst[t + i * 256] = src[t + i * 256];
    }
    __syncthreads();

    const float* x0p = g_xT + (long)(d0 + 0) * BB;
    const float* x1p = g_xT + (long)(d0 + 1) * BB;
    const float* x2p = g_xT + (long)(d0 + 2) * BB;
    const float* x3p = g_xT + (long)(d0 + 3) * BB;
    float* pout = g_part + (long)bx * BB;

#pragma unroll 2
    for (int ch = 0; ch < BB / 256; ch++) {   // 32 chunks
        int b = ch * 256 + t;
        float xs[4] = {x0p[b], x1p[b], x2p[b], x3p[b]};
        float acc = 0.f;
#pragma unroll
        for (int j = 0; j < DCH; j++) {
            float xx = xs[j];
            float fi = fmaf(xx, INVD, IOFF);
            int   i  = (int)fi;
            i = i < 0 ? 0 : (i > NC - 1 ? NC - 1 : i);
            float2 sb = scol[j * NC + i];
            acc = fmaf(sb.x, xx, acc);
            acc += sb.y;
        }
        pout[b] = acc;
    }
}

// ---------------------------------------------------------------------------
// Reduce + outer net: sum 16 partials -> sk, exact outer PWL, store.
// ---------------------------------------------------------------------------
__global__ void kan_out(float* __restrict__ out) {
    const int gid = blockIdx.x * 256 + threadIdx.x;  // 1024 blocks
    const int b = gid & (BB - 1);
    const int k = gid >> 13;

    float sk = 0.f;
#pragma unroll
    for (int j = 0; j < DD / DCH; j++)
        sk += g_part[(long)(k * (DD / DCH) + j) * BB + b];

    float r = fmaf(g_oL[k], sk, g_oC[k]);
#pragma unroll
    for (int h = 0; h < HID; h++)
        r = fmaf(g_oPack[k * 32 + h], fmaxf(sk, g_oPack[k * 32 + 16 + h]), r);

    out[(long)b * KK + k] = r;
}

// ---------------------------------------------------------------------------
extern "C" void kernel_launch(void* const* d_in, const int* in_sizes, int n_in,
                              void* d_out, int out_size) {
    const float* x   = (const float*)d_in[0];
    const float* iw1 = (const float*)d_in[1];
    const float* ib1 = (const float*)d_in[2];
    const float* iw2 = (const float*)d_in[3];
    const float* ib2 = (const float*)d_in[4];
    const float* ow1 = (const float*)d_in[5];
    const float* ob1 = (const float*)d_in[6];
    const float* ow2 = (const float*)d_in[7];
    const float* ob2 = (const float*)d_in[8];
    float* out = (float*)d_out;

    const int smem = DCH * NC * (int)sizeof(float2);   // 64 KB
    cudaFuncSetAttribute(kan_main, cudaFuncAttributeMaxDynamicSharedMemorySize, smem);

    kan_prep<<<KK * DD, 128>>>(iw1, ib1, iw2, ib2, ow1, ob1, ow2, ob2);
    kan_xT<<<BB / 64, 256>>>(x);
    kan_main<<<KK * (DD / DCH), 256, smem>>>();
    kan_out<<<(BB * KK) / 256, 256>>>(out);
}

// round 12
// speedup vs baseline: 2.1774x; 2.1774x over previous
#include <cuda_runtime.h>

#define BB 8192
#define DD 64
#define KK 32
#define HID 16

#define NC   256                  // cells per (k,d) column
#define XLO  (-6.0f)
#define INVD (256.0f / 12.0f)     // NC / 12
#define IOFF 128.0f               // -XLO * INVD (exact)
#define CW   (12.0f / 256.0f)     // cell width

#define DPB  4                    // d per main block
#define BSPL 4                    // b splits
#define BPB  (BB / BSPL)          // 2048 b per block
#define DG   (DD / DPB)           // 16 d-groups

// -------- device scratch --------
__device__ float2 g_tab[DD * NC * KK];          // 4 MB, layout [d][cell][k]
__device__ float  g_xT[DD * BB];                // 2 MB, x transposed [d][b]
__device__ float  g_part[DG * BB * KK];         // 16 MB, [dg][b][k]
__device__ float  g_oPack[KK * 32];             // outer: [0:16)=A, [16:32)=t
__device__ float  g_oL[KK];
__device__ float  g_oC[KK];

// ---------------------------------------------------------------------------
// Prep: block per d (64 blocks). Warp 0: lane k transforms + rank-sorts its
// 16 knots, builds prefix slopes/intercepts in smem. All 256 threads fill
// tab[d][cell][k] coalesced (k contiguous!).
// f(x) = sum_h A_h*max(x,t_h) + L*x + C; sorted knots -> 17 segments:
//   S_j = L + sum_{i<j} A_(i) ;  B_j = C + sum_{i>=j} P_(i),  P = A*t exact.
// ---------------------------------------------------------------------------
__global__ void kan_prep(const float* __restrict__ iw1, const float* __restrict__ ib1,
                         const float* __restrict__ iw2, const float* __restrict__ ib2,
                         const float* __restrict__ ow1, const float* __restrict__ ob1,
                         const float* __restrict__ ow2, const float* __restrict__ ob2) {
    __shared__ float sT[32][17], sS[32][17], sB[32][17];
    const int d = blockIdx.x;
    const int t = threadIdx.x;

    if (t < 32) {
        const int k = t;
        const long base = ((long)k * DD + d) * HID;
        float A[16], T[16], P[16];
        float L = 0.f, C = ib2[k * DD + d];
#pragma unroll
        for (int h = 0; h < HID; h++) {
            float a = iw1[base + h], b = ib1[base + h], c = iw2[base + h];
            float ac = a * c;
            if (a > 0.f)      { A[h] =  ac; T[h] = -b / a; P[h] = -c * b; C += c * b; }
            else if (a < 0.f) { A[h] = -ac; T[h] = -b / a; P[h] =  c * b; L += ac; }
            else              { A[h] = 0.f; T[h] = 0.f;    P[h] = 0.f;    C += c * fmaxf(b, 0.f); }
        }
        // rank sort (no indexed registers needed; scatter into smem)
#pragma unroll
        for (int i = 0; i < 16; i++) {
            float Ti = T[i];
            int r = 0;
#pragma unroll
            for (int j = 0; j < 16; j++)
                r += (T[j] < Ti) || (T[j] == Ti && j < i);
            sT[k][r] = Ti; sS[k][r] = A[i]; sB[k][r] = P[i];
        }
        // prefix: S_j (ascending), B_j (descending); read-before-overwrite safe
        float run = L;
#pragma unroll
        for (int j = 0; j <= 16; j++) {
            float aj = (j < 16) ? sS[k][j] : 0.f;
            sS[k][j] = run;
            run += aj;
        }
        float run2 = C;
        sB[k][16] = run2;
#pragma unroll
        for (int j = 15; j >= 0; j--) {
            float pj = sB[k][j];
            run2 += pj;
            sB[k][j] = run2;
        }
    }

    // Outer-net transform (exact, direct form): block 0, threads 32..63.
    if (blockIdx.x == 0 && t >= 32 && t < 64) {
        const int k = t - 32;
        float Lo = 0.f, Co = ob2[k];
#pragma unroll
        for (int h = 0; h < HID; h++) {
            float a = ow1[k * HID + h], b = ob1[k * HID + h], c = ow2[k * HID + h];
            float ac = a * c, A2, tt;
            if (a > 0.f)      { A2 = ac;  tt = -b / a; Co += c * b; }
            else if (a < 0.f) { A2 = -ac; tt = -b / a; Lo += ac; }
            else              { A2 = 0.f; tt = 0.f;    Co += c * fmaxf(b, 0.f); }
            g_oPack[k * 32 + h]      = A2;
            g_oPack[k * 32 + 16 + h] = tt;
        }
        g_oL[k] = Lo;
        g_oC[k] = Co;
    }
    __syncthreads();

    // Fill: entry e = (cell c, k); writes coalesced (k contiguous).
#pragma unroll
    for (int e = t; e < NC * KK; e += 256) {
        int c = e >> 5, k = e & 31;
        float m = XLO + (c + 0.5f) * CW;
        int j = 0;
#pragma unroll
        for (int i = 0; i < 16; i++) j += (sT[k][i] <= m) ? 1 : 0;
        g_tab[((long)d * NC + c) * KK + k] = make_float2(sS[k][j], sB[k][j]);
    }
}

// ---------------------------------------------------------------------------
// x transpose: x[b][d] -> g_xT[d][b] (proven in R11).
// ---------------------------------------------------------------------------
__global__ void kan_xT(const float* __restrict__ x) {
    __shared__ float tile[64][65];
    const int t  = threadIdx.x;       // 256
    const int b0 = blockIdx.x * 64;   // 128 blocks

#pragma unroll
    for (int i = 0; i < 4; i++) {
        int idx = t + i * 256;
        int row = idx >> 4;
        int c4  = idx & 15;
        float4 v = ((const float4*)(x + (long)(b0 + row) * DD))[c4];
        tile[row][c4 * 4 + 0] = v.x;
        tile[row][c4 * 4 + 1] = v.y;
        tile[row][c4 * 4 + 2] = v.z;
        tile[row][c4 * 4 + 3] = v.w;
    }
    __syncthreads();
#pragma unroll
    for (int i = 0; i < 4; i++) {
        int idx = t + i * 256;
        int d  = idx >> 4;
        int c4 = idx & 15;
        float4 v = make_float4(tile[c4 * 4 + 0][d], tile[c4 * 4 + 1][d],
                               tile[c4 * 4 + 2][d], tile[c4 * 4 + 3][d]);
        ((float4*)(g_xT + (long)d * BB + b0))[c4] = v;
    }
}

// ---------------------------------------------------------------------------
// Main: grid (4 bs, 16 dg, 2 kg) = 128 blocks, 512 threads, 160 KB smem.
// Lane = (half: b parity, kl: k within 16-group). Per warp-iter:
// 2 b's x 16 k x 4 d = 128 evals; all table LDS are contiguous 128B rows
// per half-warp -> deterministic 2-phase, conflict-free.
// ---------------------------------------------------------------------------
__global__ void __launch_bounds__(512, 1)
kan_main() {
    extern __shared__ float smem[];
    float2* stab = (float2*)smem;                   // DPB*NC*16 float2 = 128 KB
    float*  sxb  = smem + DPB * NC * 16 * 2;        // DPB*BPB floats  = 32 KB

    const int t  = threadIdx.x;
    const int bs = blockIdx.x, dg = blockIdx.y, kg = blockIdx.z;
    const int d0 = dg * DPB, b0 = bs * BPB;

    // stage table half (k-slab for this kg): 8192 float4
    {
        const float4* gt = (const float4*)g_tab;    // float4 = 2 float2 entries
        float4* st = (float4*)stab;
#pragma unroll
        for (int i = 0; i < 16; i++) {
            int e  = t + i * 512;
            int q  = e & 7;                         // float4 within 16-k slab
            int c  = (e >> 3) & 255;
            int dd = e >> 11;
            st[e] = gt[((long)(d0 + dd) * NC + c) * (KK / 2) + kg * 8 + q];
        }
    }
    // stage x chunk: 2048 float4
    {
        const float4* gx4 = (const float4*)g_xT;
        float4* sx4 = (float4*)sxb;
#pragma unroll
        for (int i = 0; i < 4; i++) {
            int e  = t + i * 512;
            int dd = e >> 9;
            int c  = e & 511;
            sx4[e] = gx4[((long)(d0 + dd) * BB + b0) / 4 + c];
        }
    }
    __syncthreads();

    const int w    = t >> 5, l = t & 31;
    const int kl   = l & 15;
    const int half = l >> 4;
    const int kk   = kg * 16 + kl;
    float* pbase = g_part + ((long)dg * BB + b0) * KK;

#pragma unroll 2
    for (int p = w; p < BPB / 2; p += 16) {
        int b = 2 * p + half;
        float x0 = sxb[0 * BPB + b];
        float x1 = sxb[1 * BPB + b];
        float x2 = sxb[2 * BPB + b];
        float x3 = sxb[3 * BPB + b];
        int i0 = (int)fmaf(x0, INVD, IOFF); i0 = i0 < 0 ? 0 : (i0 > NC - 1 ? NC - 1 : i0);
        int i1 = (int)fmaf(x1, INVD, IOFF); i1 = i1 < 0 ? 0 : (i1 > NC - 1 ? NC - 1 : i1);
        int i2 = (int)fmaf(x2, INVD, IOFF); i2 = i2 < 0 ? 0 : (i2 > NC - 1 ? NC - 1 : i2);
        int i3 = (int)fmaf(x3, INVD, IOFF); i3 = i3 < 0 ? 0 : (i3 > NC - 1 ? NC - 1 : i3);
        float2 s0 = stab[(0 * NC + i0) * 16 + kl];
        float2 s1 = stab[(1 * NC + i1) * 16 + kl];
        float2 s2 = stab[(2 * NC + i2) * 16 + kl];
        float2 s3 = stab[(3 * NC + i3) * 16 + kl];
        float acc = fmaf(s0.x, x0, s0.y) + fmaf(s1.x, x1, s1.y)
                  + fmaf(s2.x, x2, s2.y) + fmaf(s3.x, x3, s3.y);
        pbase[(long)b * KK + kk] = acc;
    }
}

// ---------------------------------------------------------------------------
// Out: sum 16 partials -> sk; exact outer PWL (params staged in smem).
// ---------------------------------------------------------------------------
__global__ void kan_out(float* __restrict__ out) {
    __shared__ float sop[32 * 35];        // pitch 35 (odd): conflict-free
    const int t = threadIdx.x;
#pragma unroll
    for (int e = t; e < 1024; e += 256) sop[(e >> 5) * 35 + (e & 31)] = g_oPack[e];
    if (t < 32)       sop[t * 35 + 32] = g_oL[t];
    else if (t < 64)  sop[(t - 32) * 35 + 33] = g_oC[t - 32];
    __syncthreads();

    const int gid = blockIdx.x * 256 + t;
    const int k = gid & 31;
    const int b = gid >> 5;

    float sk = 0.f;
#pragma unroll
    for (int dg = 0; dg < DG; dg++)
        sk += g_part[((long)dg * BB + b) * KK + k];

    const float* op = sop + k * 35;
    float r = fmaf(op[32], sk, op[33]);
#pragma unroll
    for (int h = 0; h < HID; h++)
        r = fmaf(op[h], fmaxf(sk, op[16 + h]), r);

    out[(long)b * KK + k] = r;
}

// ---------------------------------------------------------------------------
extern "C" void kernel_launch(void* const* d_in, const int* in_sizes, int n_in,
                              void* d_out, int out_size) {
    const float* x   = (const float*)d_in[0];
    const float* iw1 = (const float*)d_in[1];
    const float* ib1 = (const float*)d_in[2];
    const float* iw2 = (const float*)d_in[3];
    const float* ib2 = (const float*)d_in[4];
    const float* ow1 = (const float*)d_in[5];
    const float* ob1 = (const float*)d_in[6];
    const float* ow2 = (const float*)d_in[7];
    const float* ob2 = (const float*)d_in[8];
    float* out = (float*)d_out;

    const int smem = (DPB * NC * 16 * 2 + DPB * BPB) * 4;   // 163840 B
    cudaFuncSetAttribute(kan_main, cudaFuncAttributeMaxDynamicSharedMemorySize, smem);

    kan_prep<<<DD, 256>>>(iw1, ib1, iw2, ib2, ow1, ob1, ow2, ob2);
    kan_xT<<<BB / 64, 256>>>(x);
    kan_main<<<dim3(BSPL, DG, 2), 512, smem>>>();
    kan_out<<<(BB * KK) / 256, 256>>>(out);
}

// round 13
// speedup vs baseline: 2.3668x; 1.0870x over previous
#include <cuda_runtime.h>

#define BB 8192
#define DD 64
#define KK 32
#define HID 16

#define NC   128                  // cells per (k,d) column
#define XLO  (-6.0f)
#define INVD (128.0f / 12.0f)     // NC / 12
#define IOFF 64.0f                // -XLO * INVD (exact)
#define CW   (12.0f / 128.0f)     // cell width

#define DPB  8                    // d per main block
#define BSPL 8                    // b splits
#define BPB  (BB / BSPL)          // 1024 b per block
#define DG   (DD / DPB)           // 8 d-groups

// -------- device scratch --------
__device__ float2 g_tab[DD * NC * KK];          // 2 MB, layout [d][cell][k]
__device__ float  g_xT[DD * BB];                // 2 MB, x transposed [d][b]
__device__ float  g_part[DG * BB * KK];         // 8 MB, [dg][b][k]
__device__ float  g_oPack[KK * 32];             // outer: [0:16)=A, [16:32)=t
__device__ float  g_oL[KK];
__device__ float  g_oC[KK];

// ---------------------------------------------------------------------------
// Prep: block per d (64 blocks). Warp 0: lane k transforms + rank-sorts its
// 16 knots, builds prefix slopes/intercepts in smem. All 256 threads fill
// tab[d][cell][k] coalesced (k contiguous).
// f(x) = sum_h A_h*max(x,t_h) + L*x + C; sorted knots -> 17 segments:
//   S_j = L + sum_{i<j} A_(i) ;  B_j = C + sum_{i>=j} P_(i),  P = A*t exact.
// ---------------------------------------------------------------------------
__global__ void kan_prep(const float* __restrict__ iw1, const float* __restrict__ ib1,
                         const float* __restrict__ iw2, const float* __restrict__ ib2,
                         const float* __restrict__ ow1, const float* __restrict__ ob1,
                         const float* __restrict__ ow2, const float* __restrict__ ob2) {
    __shared__ float sT[32][17], sS[32][17], sB[32][17];
    const int d = blockIdx.x;
    const int t = threadIdx.x;

    if (t < 32) {
        const int k = t;
        const long base = ((long)k * DD + d) * HID;
        float A[16], T[16], P[16];
        float L = 0.f, C = ib2[k * DD + d];
#pragma unroll
        for (int h = 0; h < HID; h++) {
            float a = iw1[base + h], b = ib1[base + h], c = iw2[base + h];
            float ac = a * c;
            if (a > 0.f)      { A[h] =  ac; T[h] = -b / a; P[h] = -c * b; C += c * b; }
            else if (a < 0.f) { A[h] = -ac; T[h] = -b / a; P[h] =  c * b; L += ac; }
            else              { A[h] = 0.f; T[h] = 0.f;    P[h] = 0.f;    C += c * fmaxf(b, 0.f); }
        }
        // rank sort (scatter into smem by rank)
#pragma unroll
        for (int i = 0; i < 16; i++) {
            float Ti = T[i];
            int r = 0;
#pragma unroll
            for (int j = 0; j < 16; j++)
                r += (T[j] < Ti) || (T[j] == Ti && j < i);
            sT[k][r] = Ti; sS[k][r] = A[i]; sB[k][r] = P[i];
        }
        // prefix: S_j ascending, B_j descending
        float run = L;
#pragma unroll
        for (int j = 0; j <= 16; j++) {
            float aj = (j < 16) ? sS[k][j] : 0.f;
            sS[k][j] = run;
            run += aj;
        }
        float run2 = C;
        sB[k][16] = run2;
#pragma unroll
        for (int j = 15; j >= 0; j--) {
            float pj = sB[k][j];
            run2 += pj;
            sB[k][j] = run2;
        }
    }

    // Outer-net transform (exact): block 0, threads 32..63.
    if (blockIdx.x == 0 && t >= 32 && t < 64) {
        const int k = t - 32;
        float Lo = 0.f, Co = ob2[k];
#pragma unroll
        for (int h = 0; h < HID; h++) {
            float a = ow1[k * HID + h], b = ob1[k * HID + h], c = ow2[k * HID + h];
            float ac = a * c, A2, tt;
            if (a > 0.f)      { A2 = ac;  tt = -b / a; Co += c * b; }
            else if (a < 0.f) { A2 = -ac; tt = -b / a; Lo += ac; }
            else              { A2 = 0.f; tt = 0.f;    Co += c * fmaxf(b, 0.f); }
            g_oPack[k * 32 + h]      = A2;
            g_oPack[k * 32 + 16 + h] = tt;
        }
        g_oL[k] = Lo;
        g_oC[k] = Co;
    }
    __syncthreads();

    // Fill: entry e = (cell c, k); writes coalesced (k contiguous).
#pragma unroll
    for (int e = t; e < NC * KK; e += 256) {
        int c = e >> 5, k = e & 31;
        float m = XLO + (c + 0.5f) * CW;
        int j = 0;
#pragma unroll
        for (int i = 0; i < 16; i++) j += (sT[k][i] <= m) ? 1 : 0;
        g_tab[((long)d * NC + c) * KK + k] = make_float2(sS[k][j], sB[k][j]);
    }
}

// ---------------------------------------------------------------------------
// x transpose: x[b][d] -> g_xT[d][b].
// ---------------------------------------------------------------------------
__global__ void kan_xT(const float* __restrict__ x) {
    __shared__ float tile[64][65];
    const int t  = threadIdx.x;       // 256
    const int b0 = blockIdx.x * 64;   // 128 blocks

#pragma unroll
    for (int i = 0; i < 4; i++) {
        int idx = t + i * 256;
        int row = idx >> 4;
        int c4  = idx & 15;
        float4 v = ((const float4*)(x + (long)(b0 + row) * DD))[c4];
        tile[row][c4 * 4 + 0] = v.x;
        tile[row][c4 * 4 + 1] = v.y;
        tile[row][c4 * 4 + 2] = v.z;
        tile[row][c4 * 4 + 3] = v.w;
    }
    __syncthreads();
#pragma unroll
    for (int i = 0; i < 4; i++) {
        int idx = t + i * 256;
        int d  = idx >> 4;
        int c4 = idx & 15;
        float4 v = make_float4(tile[c4 * 4 + 0][d], tile[c4 * 4 + 1][d],
                               tile[c4 * 4 + 2][d], tile[c4 * 4 + 3][d]);
        ((float4*)(g_xT + (long)d * BB + b0))[c4] = v;
    }
}

// ---------------------------------------------------------------------------
// Main: grid (8 bs, 8 dg, 2 kg) = 128 blocks, 512 threads, 160 KB smem.
// Lane = (half: b parity, kl: k within 16-group). Per warp-iter:
// 2 b x 16 k x 8 d = 256 evals; table LDS rows are contiguous 128B per
// half-warp -> deterministic conflict-free.
// ---------------------------------------------------------------------------
__global__ void __launch_bounds__(512, 1)
kan_main() {
    extern __shared__ float smem[];
    float2* stab = (float2*)smem;                   // DPB*NC*16 float2 = 128 KB
    float*  sxb  = smem + DPB * NC * 16 * 2;        // DPB*BPB floats  = 32 KB

    const int t  = threadIdx.x;
    const int bs = blockIdx.x, dg = blockIdx.y, kg = blockIdx.z;
    const int d0 = dg * DPB, b0 = bs * BPB;

    // stage table slab (k-half): 8192 float4
    {
        const float4* gt = (const float4*)g_tab;    // float4 = 2 float2 entries
        float4* st = (float4*)stab;
#pragma unroll
        for (int i = 0; i < 16; i++) {
            int e  = t + i * 512;
            int q  = e & 7;                         // float4 within 16-k slab
            int c  = (e >> 3) & (NC - 1);
            int dd = e >> 10;
            st[e] = gt[((long)(d0 + dd) * NC + c) * (KK / 2) + kg * 8 + q];
        }
    }
    // stage x chunk: 2048 float4
    {
        const float4* gx4 = (const float4*)g_xT;
        float4* sx4 = (float4*)sxb;
#pragma unroll
        for (int i = 0; i < 4; i++) {
            int e  = t + i * 512;
            int dd = e >> 8;
            int c  = e & 255;
            sx4[e] = gx4[((long)(d0 + dd) * BB + b0) / 4 + c];
        }
    }
    __syncthreads();

    const int w    = t >> 5, l = t & 31;
    const int kl   = l & 15;
    const int half = l >> 4;
    const int kk   = kg * 16 + kl;
    float* pbase = g_part + ((long)dg * BB + b0) * KK;

#pragma unroll 2
    for (int p = w; p < BPB / 2; p += 16) {
        int b = 2 * p + half;
        float acc = 0.f;
#pragma unroll
        for (int dd = 0; dd < DPB; dd++) {
            float xx = sxb[dd * BPB + b];
            int i = (int)fmaf(xx, INVD, IOFF);
            i = i < 0 ? 0 : (i > NC - 1 ? NC - 1 : i);
            float2 sb = stab[(dd * NC + i) * 16 + kl];
            acc += fmaf(sb.x, xx, sb.y);
        }
        pbase[(long)b * KK + kk] = acc;
    }
}

// ---------------------------------------------------------------------------
// Out: thread = (b, k-quad). 8 x LDG.128 partials -> sum; exact outer PWL
// for 4 k's; STG.128. 256 blocks x 256 threads.
// ---------------------------------------------------------------------------
__global__ void kan_out(float* __restrict__ out) {
    __shared__ float sop[32 * 35];        // pitch 35: conflict-free
    const int t = threadIdx.x;
#pragma unroll
    for (int e = t; e < 1024; e += 256) sop[(e >> 5) * 35 + (e & 31)] = g_oPack[e];
    if (t < 32)       sop[t * 35 + 32] = g_oL[t];
    else if (t < 64)  sop[(t - 32) * 35 + 33] = g_oC[t - 32];
    __syncthreads();

    const int gid = blockIdx.x * 256 + t;  // 0 .. BB*8-1
    const int k4 = gid & 7;                // k-quad
    const int b  = gid >> 3;

    const float4* gp = (const float4*)g_part;
    float4 s = make_float4(0.f, 0.f, 0.f, 0.f);
#pragma unroll
    for (int dg = 0; dg < DG; dg++) {
        float4 p = gp[((long)dg * BB + b) * (KK / 4) + k4];
        s.x += p.x; s.y += p.y; s.z += p.z; s.w += p.w;
    }

    float sk[4] = {s.x, s.y, s.z, s.w};
    float4 r4;
    float* rr = (float*)&r4;
#pragma unroll
    for (int j = 0; j < 4; j++) {
        const int k = k4 * 4 + j;
        const float* op = sop + k * 35;
        float sv = sk[j];
        float r = fmaf(op[32], sv, op[33]);
#pragma unroll
        for (int h = 0; h < HID; h++)
            r = fmaf(op[h], fmaxf(sv, op[16 + h]), r);
        rr[j] = r;
    }
    ((float4*)(out + (long)b * KK))[k4] = r4;
}

// ---------------------------------------------------------------------------
extern "C" void kernel_launch(void* const* d_in, const int* in_sizes, int n_in,
                              void* d_out, int out_size) {
    const float* x   = (const float*)d_in[0];
    const float* iw1 = (const float*)d_in[1];
    const float* ib1 = (const float*)d_in[2];
    const float* iw2 = (const float*)d_in[3];
    const float* ib2 = (const float*)d_in[4];
    const float* ow1 = (const float*)d_in[5];
    const float* ob1 = (const float*)d_in[6];
    const float* ow2 = (const float*)d_in[7];
    const float* ob2 = (const float*)d_in[8];
    float* out = (float*)d_out;

    const int smem = (DPB * NC * 16 * 2 + DPB * BPB) * 4;   // 163840 B
    cudaFuncSetAttribute(kan_main, cudaFuncAttributeMaxDynamicSharedMemorySize, smem);

    kan_prep<<<DD, 256>>>(iw1, ib1, iw2, ib2, ow1, ob1, ow2, ob2);
    kan_xT<<<BB / 64, 256>>>(x);
    kan_main<<<dim3(BSPL, DG, 2), 512, smem>>>();
    kan_out<<<(BB * 8) / 256, 256>>>(out);
}

// round 14
// speedup vs baseline: 2.4976x; 1.0553x over previous
#include <cuda_runtime.h>

#define BB 8192
#define DD 64
#define KK 32
#define HID 16

#define NC   128                  // cells per (k,d) column
#define XLO  (-6.0f)
#define INVD (128.0f / 12.0f)     // NC / 12
#define IOFF 64.0f                // -XLO * INVD (exact)
#define CW   (12.0f / 128.0f)     // cell width

#define DPB  8                    // d per main block
#define BSPL 8                    // b splits
#define BPB  (BB / BSPL)          // 1024 b per block
#define DG   (DD / DPB)           // 8 d-groups

// -------- device scratch --------
__device__ float2 g_tab[DD * NC * KK];          // 2 MB, layout [d][cell][k]
__device__ float  g_part[DG * BB * KK];         // 8 MB, [dg][b][k]
__device__ float  g_oPack[KK * 32];             // outer: [0:16)=A, [16:32)=t
__device__ float  g_oL[KK];
__device__ float  g_oC[KK];

// ---------------------------------------------------------------------------
// Prep: block per d (64 blocks). Warp 0: lane k transforms + rank-sorts its
// 16 knots, builds prefix slopes/intercepts in smem. All 256 threads fill
// tab[d][cell][k] coalesced (k contiguous).
// f(x) = sum_h A_h*max(x,t_h) + L*x + C; sorted knots -> 17 segments:
//   S_j = L + sum_{i<j} A_(i) ;  B_j = C + sum_{i>=j} P_(i),  P = A*t exact.
// Thresholds via __fdividef: they only select cells, 2-ulp is irrelevant.
// ---------------------------------------------------------------------------
__global__ void kan_prep(const float* __restrict__ iw1, const float* __restrict__ ib1,
                         const float* __restrict__ iw2, const float* __restrict__ ib2,
                         const float* __restrict__ ow1, const float* __restrict__ ob1,
                         const float* __restrict__ ow2, const float* __restrict__ ob2) {
    __shared__ float sT[32][17], sS[32][17], sB[32][17];
    const int d = blockIdx.x;
    const int t = threadIdx.x;

    if (t < 32) {
        const int k = t;
        const long base = ((long)k * DD + d) * HID;
        float A[16], T[16], P[16];
        float L = 0.f, C = ib2[k * DD + d];
#pragma unroll
        for (int h = 0; h < HID; h++) {
            float a = iw1[base + h], b = ib1[base + h], c = iw2[base + h];
            float ac = a * c;
            if (a > 0.f)      { A[h] =  ac; T[h] = __fdividef(-b, a); P[h] = -c * b; C += c * b; }
            else if (a < 0.f) { A[h] = -ac; T[h] = __fdividef(-b, a); P[h] =  c * b; L += ac; }
            else              { A[h] = 0.f; T[h] = 0.f;    P[h] = 0.f;    C += c * fmaxf(b, 0.f); }
        }
        // rank sort (scatter into smem by rank)
#pragma unroll
        for (int i = 0; i < 16; i++) {
            float Ti = T[i];
            int r = 0;
#pragma unroll
            for (int j = 0; j < 16; j++)
                r += (T[j] < Ti) || (T[j] == Ti && j < i);
            sT[k][r] = Ti; sS[k][r] = A[i]; sB[k][r] = P[i];
        }
        // prefix: S_j ascending, B_j descending
        float run = L;
#pragma unroll
        for (int j = 0; j <= 16; j++) {
            float aj = (j < 16) ? sS[k][j] : 0.f;
            sS[k][j] = run;
            run += aj;
        }
        float run2 = C;
        sB[k][16] = run2;
#pragma unroll
        for (int j = 15; j >= 0; j--) {
            float pj = sB[k][j];
            run2 += pj;
            sB[k][j] = run2;
        }
    }

    // Outer-net transform (exact, full-precision div): block 0, threads 32..63.
    if (blockIdx.x == 0 && t >= 32 && t < 64) {
        const int k = t - 32;
        float Lo = 0.f, Co = ob2[k];
#pragma unroll
        for (int h = 0; h < HID; h++) {
            float a = ow1[k * HID + h], b = ob1[k * HID + h], c = ow2[k * HID + h];
            float ac = a * c, A2, tt;
            if (a > 0.f)      { A2 = ac;  tt = -b / a; Co += c * b; }
            else if (a < 0.f) { A2 = -ac; tt = -b / a; Lo += ac; }
            else              { A2 = 0.f; tt = 0.f;    Co += c * fmaxf(b, 0.f); }
            g_oPack[k * 32 + h]      = A2;
            g_oPack[k * 32 + 16 + h] = tt;
        }
        g_oL[k] = Lo;
        g_oC[k] = Co;
    }
    __syncthreads();

    // Fill: entry e = (cell c, k); writes coalesced (k contiguous).
#pragma unroll
    for (int e = t; e < NC * KK; e += 256) {
        int c = e >> 5, k = e & 31;
        float m = XLO + (c + 0.5f) * CW;
        int j = 0;
#pragma unroll
        for (int i = 0; i < 16; i++) j += (sT[k][i] <= m) ? 1 : 0;
        g_tab[((long)d * NC + c) * KK + k] = make_float2(sS[k][j], sB[k][j]);
    }
}

// ---------------------------------------------------------------------------
// Main: grid (8 bs, 8 dg, 2 kg) = 128 blocks, 512 threads, 160 KB smem.
// x staged in-kernel: per b, the 8 needed d's are one 32B-aligned 32B slice
// (2 x LDG.128 + 8 conflict-free STS.32) -- no separate transpose kernel.
// Lane = (half: b parity, kl: k within 16-group). Table LDS rows are
// contiguous 128B per half-warp -> deterministic conflict-free.
// ---------------------------------------------------------------------------
__global__ void __launch_bounds__(512, 1)
kan_main(const float* __restrict__ x) {
    extern __shared__ float smem[];
    float2* stab = (float2*)smem;                   // DPB*NC*16 float2 = 128 KB
    float*  sxb  = smem + DPB * NC * 16 * 2;        // DPB*BPB floats  = 32 KB

    const int t  = threadIdx.x;
    const int bs = blockIdx.x, dg = blockIdx.y, kg = blockIdx.z;
    const int d0 = dg * DPB, b0 = bs * BPB;

    // stage table slab (k-half): 8192 float4
    {
        const float4* gt = (const float4*)g_tab;    // float4 = 2 float2 entries
        float4* st = (float4*)stab;
#pragma unroll
        for (int i = 0; i < 16; i++) {
            int e  = t + i * 512;
            int q  = e & 7;                         // float4 within 16-k slab
            int c  = (e >> 3) & (NC - 1);
            int dd = e >> 10;
            st[e] = gt[((long)(d0 + dd) * NC + c) * (KK / 2) + kg * 8 + q];
        }
    }
    // stage x chunk: per b, 8 floats (32B-aligned slice of the 64-float row)
    {
#pragma unroll
        for (int i = 0; i < BPB / 512; i++) {       // 2 iters
            int b = t + i * 512;
            const float4* xr = (const float4*)(x + (long)(b0 + b) * DD + d0);
            float4 v0 = xr[0], v1 = xr[1];
            sxb[0 * BPB + b] = v0.x;
            sxb[1 * BPB + b] = v0.y;
            sxb[2 * BPB + b] = v0.z;
            sxb[3 * BPB + b] = v0.w;
            sxb[4 * BPB + b] = v1.x;
            sxb[5 * BPB + b] = v1.y;
            sxb[6 * BPB + b] = v1.z;
            sxb[7 * BPB + b] = v1.w;
        }
    }
    __syncthreads();

    const int w    = t >> 5, l = t & 31;
    const int kl   = l & 15;
    const int half = l >> 4;
    const int kk   = kg * 16 + kl;
    float* pbase = g_part + ((long)dg * BB + b0) * KK;

#pragma unroll 2
    for (int p = w; p < BPB / 2; p += 16) {
        int b = 2 * p + half;
        float acc = 0.f;
#pragma unroll
        for (int dd = 0; dd < DPB; dd++) {
            float xx = sxb[dd * BPB + b];
            int i = (int)fmaf(xx, INVD, IOFF);
            i = i < 0 ? 0 : (i > NC - 1 ? NC - 1 : i);
            float2 sb = stab[(dd * NC + i) * 16 + kl];
            acc += fmaf(sb.x, xx, sb.y);
        }
        pbase[(long)b * KK + kk] = acc;
    }
}

// ---------------------------------------------------------------------------
// Out: thread-PAIR per (b, k-quad). Each thread sums 4 dg's (4 x LDG.128,
// MLP 4), pair combines via shfl_xor(1); even lane runs exact outer PWL and
// stores STG.128. 512 blocks x 256 threads = 131072 threads.
// ---------------------------------------------------------------------------
__global__ void kan_out(float* __restrict__ out) {
    __shared__ float sop[32 * 35];        // pitch 35: conflict-free
    const int t = threadIdx.x;
#pragma unroll
    for (int e = t; e < 1024; e += 256) sop[(e >> 5) * 35 + (e & 31)] = g_oPack[e];
    if (t < 32)       sop[t * 35 + 32] = g_oL[t];
    else if (t < 64)  sop[(t - 32) * 35 + 33] = g_oC[t - 32];
    __syncthreads();

    const int gid  = blockIdx.x * 256 + t;  // 0 .. BB*16-1
    const int half = gid & 1;               // dg-half
    const int oid  = gid >> 1;              // output id: 0 .. BB*8-1
    const int k4   = oid & 7;               // k-quad
    const int b    = oid >> 3;

    const float4* gp = (const float4*)g_part;
    float4 s = make_float4(0.f, 0.f, 0.f, 0.f);
#pragma unroll
    for (int j = 0; j < 4; j++) {
        int dg = half * 4 + j;
        float4 p = gp[((long)dg * BB + b) * (KK / 4) + k4];
        s.x += p.x; s.y += p.y; s.z += p.z; s.w += p.w;
    }
    // pair combine (lanes l and l^1 share oid)
    s.x += __shfl_xor_sync(0xffffffffu, s.x, 1);
    s.y += __shfl_xor_sync(0xffffffffu, s.y, 1);
    s.z += __shfl_xor_sync(0xffffffffu, s.z, 1);
    s.w += __shfl_xor_sync(0xffffffffu, s.w, 1);

    if (half == 0) {
        float sk[4] = {s.x, s.y, s.z, s.w};
        float4 r4;
        float* rr = (float*)&r4;
#pragma unroll
        for (int j = 0; j < 4; j++) {
            const int k = k4 * 4 + j;
            const float* op = sop + k * 35;
            float sv = sk[j];
            float r = fmaf(op[32], sv, op[33]);
#pragma unroll
            for (int h = 0; h < HID; h++)
                r = fmaf(op[h], fmaxf(sv, op[16 + h]), r);
            rr[j] = r;
        }
        ((float4*)(out + (long)b * KK))[k4] = r4;
    }
}

// ---------------------------------------------------------------------------
extern "C" void kernel_launch(void* const* d_in, const int* in_sizes, int n_in,
                              void* d_out, int out_size) {
    const float* x   = (const float*)d_in[0];
    const float* iw1 = (const float*)d_in[1];
    const float* ib1 = (const float*)d_in[2];
    const float* iw2 = (const float*)d_in[3];
    const float* ib2 = (const float*)d_in[4];
    const float* ow1 = (const float*)d_in[5];
    const float* ob1 = (const float*)d_in[6];
    const float* ow2 = (const float*)d_in[7];
    const float* ob2 = (const float*)d_in[8];
    float* out = (float*)d_out;

    const int smem = (DPB * NC * 16 * 2 + DPB * BPB) * 4;   // 163840 B
    cudaFuncSetAttribute(kan_main, cudaFuncAttributeMaxDynamicSharedMemorySize, smem);

    kan_prep<<<DD, 256>>>(iw1, ib1, iw2, ib2, ow1, ob1, ow2, ob2);
    kan_main<<<dim3(BSPL, DG, 2), 512, smem>>>(x);
    kan_out<<<(BB * 16) / 256, 256>>>(out);
}

// round 15
// speedup vs baseline: 2.5486x; 1.0204x over previous
#include <cuda_runtime.h>

#define BB 8192
#define DD 64
#define KK 32
#define HID 16

#define NC   128                  // cells per (k,d) column
#define XLO  (-6.0f)
#define INVD (128.0f / 12.0f)     // NC / 12
#define IOFF 64.0f                // -XLO * INVD (exact)
#define CW   (12.0f / 128.0f)     // cell width

#define DPB  8                    // d per main block
#define BSPL 8                    // b splits
#define BPB  (BB / BSPL)          // 1024 b per block
#define DG   (DD / DPB)           // 8 d-groups

// -------- device scratch --------
__device__ float2 g_tab[DD * NC * KK];          // 2 MB, layout [d][cell][k]
__device__ float  g_part[DG * BB * KK];         // 8 MB, [dg][b][k]
__device__ float  g_oPack[KK * 32];             // outer: [0:16)=A, [16:32)=t
__device__ float  g_oL[KK];
__device__ float  g_oC[KK];

// ---------------------------------------------------------------------------
// Prep: block per d (64 blocks), 512 threads = one per (k,h).
// f(x) = sum_h A_h*max(x,t_h) + L*x + C; sorted knots -> 17 segments:
//   S_j = L + sum_{i<j} A_(i) ;  B_j = C + sum_{i>=j} P_(i),  P = A*t exact.
// Parallel: per-element transform, shfl-reduce L/C, parallel rank-scatter;
// only the 17-step prefix is serial (32 threads).
// ---------------------------------------------------------------------------
__global__ void __launch_bounds__(512, 2)
kan_prep(const float* __restrict__ iw1, const float* __restrict__ ib1,
         const float* __restrict__ iw2, const float* __restrict__ ib2,
         const float* __restrict__ ow1, const float* __restrict__ ob1,
         const float* __restrict__ ow2, const float* __restrict__ ob2) {
    __shared__ float sT0[32][16];
    __shared__ float sTs[32][16], sS[32][17], sB[32][17];
    __shared__ float sL[32], sC[32];
    const int d = blockIdx.x;
    const int t = threadIdx.x;        // 512
    const int k = t >> 4, h = t & 15;

    // per-element transform (coalesced: h contiguous)
    const long base = ((long)k * DD + d) * HID + h;
    float a = iw1[base], b = ib1[base], c = iw2[base];
    float ac = a * c;
    float A, T, P, Lc = 0.f, Cc = 0.f;
    if (a > 0.f)      { A =  ac; T = __fdividef(-b, a); P = -c * b; Cc = c * b; }
    else if (a < 0.f) { A = -ac; T = __fdividef(-b, a); P =  c * b; Lc = ac; }
    else              { A = 0.f; T = 0.f;               P = 0.f;    Cc = c * fmaxf(b, 0.f); }
    sT0[k][h] = T;

    // reduce L, C over h (width-16 groups align with k)
#pragma unroll
    for (int o = 8; o > 0; o >>= 1) {
        Lc += __shfl_xor_sync(0xffffffffu, Lc, o, 16);
        Cc += __shfl_xor_sync(0xffffffffu, Cc, o, 16);
    }
    if (h == 0) { sL[k] = Lc; sC[k] = Cc + ib2[k * DD + d]; }
    __syncthreads();

    // parallel rank + scatter
    {
        int r = 0;
#pragma unroll
        for (int j = 0; j < 16; j++) {
            float Tj = sT0[k][j];
            r += (Tj < T) || (Tj == T && j < h);
        }
        sTs[k][r] = T;
        sS[k][r]  = A;    // slopes by rank (pre-prefix)
        sB[k][r]  = P;    // P by rank (pre-prefix)
    }
    __syncthreads();

    // serial prefixes (trivial): S ascending from L, B descending from C
    if (t < 32) {
        const int kk = t;
        float run = sL[kk];
#pragma unroll
        for (int j = 0; j <= 16; j++) {
            float aj = (j < 16) ? sS[kk][j] : 0.f;
            sS[kk][j] = run;
            run += aj;
        }
        float run2 = sC[kk];
        sB[kk][16] = run2;
#pragma unroll
        for (int j = 15; j >= 0; j--) {
            float pj = sB[kk][j];
            run2 += pj;
            sB[kk][j] = run2;
        }
    }

    // outer-net transform (exact): block 0, threads 32..63
    if (blockIdx.x == 0 && t >= 32 && t < 64) {
        const int kk = t - 32;
        float Lo = 0.f, Co = ob2[kk];
#pragma unroll
        for (int hh = 0; hh < HID; hh++) {
            float aa = ow1[kk * HID + hh], bb = ob1[kk * HID + hh], cc = ow2[kk * HID + hh];
            float aacc = aa * cc, A2, tt;
            if (aa > 0.f)      { A2 = aacc;  tt = -bb / aa; Co += cc * bb; }
            else if (aa < 0.f) { A2 = -aacc; tt = -bb / aa; Lo += aacc; }
            else               { A2 = 0.f;   tt = 0.f;      Co += cc * fmaxf(bb, 0.f); }
            g_oPack[kk * 32 + hh]      = A2;
            g_oPack[kk * 32 + 16 + hh] = tt;
        }
        g_oL[kk] = Lo;
        g_oC[kk] = Co;
    }
    __syncthreads();

    // fill: entry e = (cell c, k); writes coalesced (k contiguous)
#pragma unroll
    for (int e = t; e < NC * KK; e += 512) {    // 8 iters
        int cc = e >> 5, kk = e & 31;
        float m = XLO + (cc + 0.5f) * CW;
        int j = 0;
#pragma unroll
        for (int i = 0; i < 16; i++) j += (sTs[kk][i] <= m) ? 1 : 0;
        g_tab[((long)d * NC + cc) * KK + kk] = make_float2(sS[kk][j], sB[kk][j]);
    }
}

// ---------------------------------------------------------------------------
// Main: grid (8 bs, 8 dg, 2 kg) = 128 blocks, 512 threads, 160 KB smem.
// x staged in-kernel (per b: one 32B-aligned 32B slice). Lane = (half: b
// parity, kl: k within 16-group). Table LDS rows are contiguous 128B per
// half-warp -> deterministic conflict-free.
// ---------------------------------------------------------------------------
__global__ void __launch_bounds__(512, 1)
kan_main(const float* __restrict__ x) {
    extern __shared__ float smem[];
    float2* stab = (float2*)smem;                   // DPB*NC*16 float2 = 128 KB
    float*  sxb  = smem + DPB * NC * 16 * 2;        // DPB*BPB floats  = 32 KB

    const int t  = threadIdx.x;
    const int bs = blockIdx.x, dg = blockIdx.y, kg = blockIdx.z;
    const int d0 = dg * DPB, b0 = bs * BPB;

    // stage table slab (k-half): 8192 float4
    {
        const float4* gt = (const float4*)g_tab;    // float4 = 2 float2 entries
        float4* st = (float4*)stab;
#pragma unroll
        for (int i = 0; i < 16; i++) {
            int e  = t + i * 512;
            int q  = e & 7;
            int c  = (e >> 3) & (NC - 1);
            int dd = e >> 10;
            st[e] = gt[((long)(d0 + dd) * NC + c) * (KK / 2) + kg * 8 + q];
        }
    }
    // stage x chunk
    {
#pragma unroll
        for (int i = 0; i < BPB / 512; i++) {       // 2 iters
            int b = t + i * 512;
            const float4* xr = (const float4*)(x + (long)(b0 + b) * DD + d0);
            float4 v0 = xr[0], v1 = xr[1];
            sxb[0 * BPB + b] = v0.x;
            sxb[1 * BPB + b] = v0.y;
            sxb[2 * BPB + b] = v0.z;
            sxb[3 * BPB + b] = v0.w;
            sxb[4 * BPB + b] = v1.x;
            sxb[5 * BPB + b] = v1.y;
            sxb[6 * BPB + b] = v1.z;
            sxb[7 * BPB + b] = v1.w;
        }
    }
    __syncthreads();

    const int w    = t >> 5, l = t & 31;
    const int kl   = l & 15;
    const int half = l >> 4;
    const int kk   = kg * 16 + kl;
    float* pbase = g_part + ((long)dg * BB + b0) * KK;

#pragma unroll 2
    for (int p = w; p < BPB / 2; p += 16) {
        int b = 2 * p + half;
        float acc = 0.f;
#pragma unroll
        for (int dd = 0; dd < DPB; dd++) {
            float xx = sxb[dd * BPB + b];
            int i = (int)fmaf(xx, INVD, IOFF);
            i = i < 0 ? 0 : (i > NC - 1 ? NC - 1 : i);
            float2 sb = stab[(dd * NC + i) * 16 + kl];
            acc += fmaf(sb.x, xx, sb.y);
        }
        pbase[(long)b * KK + kk] = acc;
    }
}

// ---------------------------------------------------------------------------
// Out: thread-PAIR per (b, k-quad). Each thread sums 4 dg's (4 x LDG.128),
// pair combines via shfl_xor(1); even lane runs exact outer PWL + STG.128.
// ---------------------------------------------------------------------------
__global__ void kan_out(float* __restrict__ out) {
    __shared__ float sop[32 * 35];        // pitch 35: conflict-free
    const int t = threadIdx.x;
#pragma unroll
    for (int e = t; e < 1024; e += 256) sop[(e >> 5) * 35 + (e & 31)] = g_oPack[e];
    if (t < 32)       sop[t * 35 + 32] = g_oL[t];
    else if (t < 64)  sop[(t - 32) * 35 + 33] = g_oC[t - 32];
    __syncthreads();

    const int gid  = blockIdx.x * 256 + t;  // 0 .. BB*16-1
    const int half = gid & 1;
    const int oid  = gid >> 1;
    const int k4   = oid & 7;
    const int b    = oid >> 3;

    const float4* gp = (const float4*)g_part;
    float4 s = make_float4(0.f, 0.f, 0.f, 0.f);
#pragma unroll
    for (int j = 0; j < 4; j++) {
        int dg = half * 4 + j;
        float4 p = gp[((long)dg * BB + b) * (KK / 4) + k4];
        s.x += p.x; s.y += p.y; s.z += p.z; s.w += p.w;
    }
    s.x += __shfl_xor_sync(0xffffffffu, s.x, 1);
    s.y += __shfl_xor_sync(0xffffffffu, s.y, 1);
    s.z += __shfl_xor_sync(0xffffffffu, s.z, 1);
    s.w += __shfl_xor_sync(0xffffffffu, s.w, 1);

    if (half == 0) {
        float sk[4] = {s.x, s.y, s.z, s.w};
        float4 r4;
        float* rr = (float*)&r4;
#pragma unroll
        for (int j = 0; j < 4; j++) {
            const int k = k4 * 4 + j;
            const float* op = sop + k * 35;
            float sv = sk[j];
            float r = fmaf(op[32], sv, op[33]);
#pragma unroll
            for (int h = 0; h < HID; h++)
                r = fmaf(op[h], fmaxf(sv, op[16 + h]), r);
            rr[j] = r;
        }
        ((float4*)(out + (long)b * KK))[k4] = r4;
    }
}

// ---------------------------------------------------------------------------
extern "C" void kernel_launch(void* const* d_in, const int* in_sizes, int n_in,
                              void* d_out, int out_size) {
    const float* x   = (const float*)d_in[0];
    const float* iw1 = (const float*)d_in[1];
    const float* ib1 = (const float*)d_in[2];
    const float* iw2 = (const float*)d_in[3];
    const float* ib2 = (const float*)d_in[4];
    const float* ow1 = (const float*)d_in[5];
    const float* ob1 = (const float*)d_in[6];
    const float* ow2 = (const float*)d_in[7];
    const float* ob2 = (const float*)d_in[8];
    float* out = (float*)d_out;

    const int smem = (DPB * NC * 16 * 2 + DPB * BPB) * 4;   // 163840 B
    cudaFuncSetAttribute(kan_main, cudaFuncAttributeMaxDynamicSharedMemorySize, smem);

    kan_prep<<<DD, 512>>>(iw1, ib1, iw2, ib2, ow1, ob1, ow2, ob2);
    kan_main<<<dim3(BSPL, DG, 2), 512, smem>>>(x);
    kan_out<<<(BB * 16) / 256, 256>>>(out);
}